// round 5
// baseline (speedup 1.0000x reference)
#include <cuda_runtime.h>
#include <cuda_fp16.h>
#include <math.h>
#include <stdint.h>

// ---------------------------------------------------------------------------
// Problem constants
// ---------------------------------------------------------------------------
#define BATCH 32
#define CIN   256
#define COUT  256
#define HW_H  56
#define HW_W  56
#define HW    3136
#define KTAPS 9
#define M_TOT (BATCH * HW)               // 100352

#define M_TILE   128
#define THREADS  256
#define NSTEPS   36                       // 4 ci-chunks x 9 taps

// A superset tile: rows m0-57 .. m0+184 (242 rows), per 64-ci chunk
#define R_A      248                      // 242 data rows + zero rows
#define ZROW     244                      // guaranteed-zero row
#define A_TILE_B (R_A * 128)              // 31744 bytes per ci-chunk
#define A_REGION (4 * A_TILE_B)           // 126976
#define B_TILE_B 32768                    // 256 oc x 64 ci fp16
#define SMEM_DYN (A_REGION + 3 * B_TILE_B) // 225280

// ---------------------------------------------------------------------------
// Global scratch
// ---------------------------------------------------------------------------
__device__ __align__(16) __half g_a[(size_t)M_TOT * CIN];    // NHWC fp16
__device__ __align__(16) __half g_w[KTAPS * COUT * CIN];     // [tap][oc][ci]

// ---------------------------------------------------------------------------
// PTX helpers (compute_103-safe: sm_80-class features only)
// ---------------------------------------------------------------------------
__device__ __forceinline__ uint32_t smem_u32(const void* p) {
    uint32_t a;
    asm("{ .reg .u64 t; cvta.to.shared.u64 t, %1; cvt.u32.u64 %0, t; }"
        : "=r"(a) : "l"(p));
    return a;
}
#define CP_ASYNC16(dst, src, sz) \
    asm volatile("cp.async.ca.shared.global [%0], [%1], 16, %2;" \
        :: "r"(dst), "l"(src), "r"(sz) : "memory")
#define CP_COMMIT() asm volatile("cp.async.commit_group;" ::: "memory")
#define CP_WAIT1()  asm volatile("cp.async.wait_group 1;" ::: "memory")

#define LDSM_X4(r, addr) \
    asm volatile("ldmatrix.sync.aligned.m8n8.x4.shared.b16 {%0,%1,%2,%3}, [%4];" \
        : "=r"((r)[0]), "=r"((r)[1]), "=r"((r)[2]), "=r"((r)[3]) : "r"(addr))

#define MMA16816(d, a, b0v, b1v) \
    asm volatile("mma.sync.aligned.m16n8k16.row.col.f32.f16.f16.f32 " \
        "{%0,%1,%2,%3}, {%4,%5,%6,%7}, {%8,%9}, {%0,%1,%2,%3};" \
        : "+f"((d)[0]), "+f"((d)[1]), "+f"((d)[2]), "+f"((d)[3]) \
        : "r"((a)[0]), "r"((a)[1]), "r"((a)[2]), "r"((a)[3]), \
          "r"(b0v), "r"(b1v))

// ---------------------------------------------------------------------------
// Kernel 1: binarize + fp16 + NCHW->NHWC. Conflict-free half2 smem transpose.
// Tile: 32 ci x 64 positions.
// ---------------------------------------------------------------------------
__global__ void binsplit_kernel(const float* __restrict__ x) {
    __shared__ __half2 s[32][33];            // [pair_pos][ci], pad 33
    const int n = blockIdx.z, ci0 = blockIdx.y * 32, pos0 = blockIdx.x * 64;
    const int tid = threadIdx.x;

    #pragma unroll
    for (int i = 0; i < 4; i++) {
        int unit = tid + i * 256;
        int cl = unit >> 5;              // ci 0..31 (fixed per warp)
        int pp = unit & 31;              // pair index = lane
        float2 v = *reinterpret_cast<const float2*>(
            x + ((size_t)(n * CIN + ci0 + cl) * HW + pos0 + pp * 2));
        float m = 0.5f * (fabsf(v.x) + fabsf(v.y));
        float a = (v.x == 0.0f) ? 0.0f : copysignf(m, v.x);
        float b = (v.y == 0.0f) ? 0.0f : copysignf(m, v.y);
        s[pp][cl] = __halves2half2(__float2half(a), __float2half(b));
    }
    __syncthreads();

    const int pl = tid >> 2;             // position 0..63
    const int c8 = tid & 3;              // 8-ci group
    const int pp = pl >> 1;
    const int hi = pl & 1;

    uint32_t w[4];
    #pragma unroll
    for (int k = 0; k < 4; k++) {
        __half2 t0 = s[pp][c8 * 8 + 2 * k];
        __half2 t1 = s[pp][c8 * 8 + 2 * k + 1];
        __half a0 = hi ? __high2half(t0) : __low2half(t0);
        __half a1 = hi ? __high2half(t1) : __low2half(t1);
        w[k] = (uint32_t)__half_as_ushort(a0) |
               ((uint32_t)__half_as_ushort(a1) << 16);
    }
    size_t dst = ((size_t)n * HW + pos0 + pl) * CIN + ci0 + c8 * 8;
    *reinterpret_cast<uint4*>(g_a + dst) = make_uint4(w[0], w[1], w[2], w[3]);
}

// ---------------------------------------------------------------------------
// Kernel 2: weights OIHW -> fp16 [tap][oc][ci]
// ---------------------------------------------------------------------------
__global__ void wsplit_kernel(const float* __restrict__ w) {
    int idx = blockIdx.x * blockDim.x + threadIdx.x;
    if (idx >= COUT * CIN * KTAPS) return;
    int oc  = idx / (CIN * KTAPS);
    int rem = idx % (CIN * KTAPS);
    int ci  = rem / KTAPS;
    int tap = rem % KTAPS;
    g_w[((size_t)tap * COUT + oc) * CIN + ci] = __float2half(w[idx]);
}

// ---------------------------------------------------------------------------
// Kernel 3: implicit-GEMM conv. A superset resident in smem (all taps, all ci);
// K loop streams only B. 8 warps, warp tile 64M x 64N.
// ---------------------------------------------------------------------------
__global__ __launch_bounds__(THREADS, 1)
void conv_hmma_kernel(const float* __restrict__ bias, float* __restrict__ out) {
    extern __shared__ __align__(1024) char smem[];
    __shared__ float s_bias[COUT];

    const int tid  = threadIdx.x;
    const int warp = tid >> 5;
    const int lane = tid & 31;
    const int m0   = blockIdx.x * M_TILE;
    const uint32_t sb = smem_u32(smem);

    s_bias[tid] = bias[tid];

    // ---- A prologue: 4 cic tiles x 248 rows x 8 segs, zero-filled halos ----
    #pragma unroll
    for (int i = 0; i < 31; i++) {                      // 7936 units / 256
        int unit = tid + i * 256;
        int cic  = unit / 1984;
        int rem  = unit - cic * 1984;
        int row  = rem >> 3;
        int seg  = rem & 7;
        int m    = m0 - 57 + row;
        bool v   = (row < 242) && (m >= 0) && (m < M_TOT);
        int mc   = m < 0 ? 0 : (m >= M_TOT ? M_TOT - 1 : m);
        const __half* src = g_a + (size_t)mc * CIN + cic * 64 + seg * 8;
        uint32_t dst = sb + cic * A_TILE_B + row * 128 +
                       (((seg ^ (row & 7)) << 4));
        CP_ASYNC16(dst, src, v ? 16 : 0);
    }
    CP_COMMIT();                                        // group: A

    // ---- B producer geometry ----
    uint32_t b_dst[8]; int b_off[8];
    #pragma unroll
    for (int i = 0; i < 8; i++) {
        int unit = tid + i * 256;
        int row = unit >> 3, seg = unit & 7;
        b_dst[i] = (uint32_t)(row * 128 + ((seg ^ (row & 7)) << 4));
        b_off[i] = row * CIN + seg * 8;
    }
    auto load_B = [&](int tap, int cic, int buf) {
        uint32_t bb = sb + A_REGION + buf * B_TILE_B;
        const __half* wsrc = g_w + (size_t)tap * COUT * CIN + cic * 64;
        #pragma unroll
        for (int i = 0; i < 8; i++)
            CP_ASYNC16(bb + b_dst[i], wsrc + b_off[i], 16);
    };

    load_B(0, 0, 0); CP_COMMIT();
    load_B(1, 0, 1); CP_COMMIT();

    // ---- consumer geometry ----
    const int wm = warp >> 2, wn = warp & 3;            // 2 x 4 warp grid
    int hh[4], ww[4], r0[4];
    #pragma unroll
    for (int mt = 0; mt < 4; mt++) {
        int m_local = wm * 64 + mt * 16 + (lane & 15);
        int m   = m0 + m_local;
        int pos = m % HW;
        hh[mt] = pos / HW_W;
        ww[mt] = pos - hh[mt] * HW_W;
        r0[mt] = m_local + 57;
    }
    const int ach = lane >> 4;
    int brow[4], br7[4];
    #pragma unroll
    for (int ng = 0; ng < 4; ng++) {
        brow[ng] = wn * 64 + (lane & 7) + ((lane >> 4) << 3) + ng * 16;
        br7[ng]  = (brow[ng] & 7) << 4;
    }
    const int bch = (lane >> 3) & 1;

    float acc[4][8][4];
    #pragma unroll
    for (int i = 0; i < 4; i++)
        #pragma unroll
        for (int j = 0; j < 8; j++)
            #pragma unroll
            for (int k = 0; k < 4; k++) acc[i][j][k] = 0.0f;

    auto compute = [&](int tap, int cic, int buf) {
        const int dy = tap / 3 - 1, dx = tap % 3 - 1;
        const int shift = dy * HW_W + dx;
        uint32_t arb[4]; int ar7[4];
        #pragma unroll
        for (int mt = 0; mt < 4; mt++) {
            int h2 = hh[mt] + dy, w2 = ww[mt] + dx;
            bool v = ((unsigned)h2 < HW_H) && ((unsigned)w2 < HW_W);
            int row = v ? (r0[mt] + shift) : ZROW;
            arb[mt] = sb + cic * A_TILE_B + row * 128;
            ar7[mt] = (row & 7) << 4;
        }
        uint32_t Bb = sb + A_REGION + buf * B_TILE_B;
        #pragma unroll
        for (int ks = 0; ks < 4; ks++) {
            uint32_t a[4][4], b[4][4];
            #pragma unroll
            for (int mt = 0; mt < 4; mt++) {
                uint32_t addr = arb[mt] + ((((ks * 2 + ach) << 4)) ^ ar7[mt]);
                LDSM_X4(a[mt], addr);
            }
            #pragma unroll
            for (int ng = 0; ng < 4; ng++) {
                uint32_t addr = Bb + brow[ng] * 128 +
                                ((((ks * 2 + bch) << 4)) ^ br7[ng]);
                LDSM_X4(b[ng], addr);
            }
            #pragma unroll
            for (int mt = 0; mt < 4; mt++)
                #pragma unroll
                for (int ng = 0; ng < 4; ng++) {
                    MMA16816(acc[mt][2 * ng],     a[mt], b[ng][0], b[ng][1]);
                    MMA16816(acc[mt][2 * ng + 1], a[mt], b[ng][2], b[ng][3]);
                }
        }
    };

    // ---- main loop: stream B only ----
    int tap = 0, cic = 0;
    #pragma unroll 1
    for (int s = 0; s < NSTEPS; s++) {
        CP_WAIT1();
        __syncthreads();
        int s2 = s + 2;
        if (s2 < NSTEPS) load_B(s2 % 9, s2 / 9, s2 % 3);
        CP_COMMIT();
        compute(tap, cic, s % 3);
        if (++tap == 9) { tap = 0; cic++; }
    }

    // ---- epilogue: smem transpose -> coalesced NCHW stores + bias ----
    __syncthreads();
    float* epi = reinterpret_cast<float*>(smem) + warp * (64 * 33);
    #pragma unroll 1
    for (int mh = 0; mh < 2; mh++) {
        #pragma unroll
        for (int mtl = 0; mtl < 2; mtl++) {
            int mt = mh * 2 + mtl;
            #pragma unroll
            for (int nt = 0; nt < 8; nt++) {
                int nloc = nt * 8 + (lane & 3) * 2;
                int mloc = mtl * 16 + (lane >> 2);
                epi[ nloc      * 33 + mloc    ] = acc[mt][nt][0];
                epi[(nloc + 1) * 33 + mloc    ] = acc[mt][nt][1];
                epi[ nloc      * 33 + mloc + 8] = acc[mt][nt][2];
                epi[(nloc + 1) * 33 + mloc + 8] = acc[mt][nt][3];
            }
        }
        __syncwarp();
        int m   = m0 + wm * 64 + mh * 32 + lane;
        int img = m / HW, pos = m % HW;
        float* ob = out + (size_t)img * COUT * HW + pos;
        #pragma unroll 4
        for (int nloc = 0; nloc < 64; nloc++) {
            int oc = wn * 64 + nloc;
            ob[(size_t)oc * HW] = epi[nloc * 33 + lane] + s_bias[oc];
        }
        __syncwarp();
    }
}

// ---------------------------------------------------------------------------
// Launch
// ---------------------------------------------------------------------------
extern "C" void kernel_launch(void* const* d_in, const int* in_sizes, int n_in,
                              void* d_out, int out_size) {
    const float* x      = (const float*)d_in[0];   // [32,256,56,56]
    const float* weight = (const float*)d_in[1];   // [256,256,3,3]
    const float* bias   = (const float*)d_in[2];   // [256]
    float* out = (float*)d_out;

    {
        dim3 grid(HW / 64, CIN / 32, BATCH);       // (49, 8, 32)
        binsplit_kernel<<<grid, 256>>>(x);
    }
    {
        int n = COUT * CIN * KTAPS;
        wsplit_kernel<<<(n + 255) / 256, 256>>>(weight);
    }
    {
        cudaFuncSetAttribute(conv_hmma_kernel,
                             cudaFuncAttributeMaxDynamicSharedMemorySize,
                             SMEM_DYN);
        int m_tiles = M_TOT / M_TILE;              // 784
        conv_hmma_kernel<<<m_tiles, THREADS, SMEM_DYN>>>(bias, out);
    }
    (void)in_sizes; (void)n_in; (void)out_size;
}